// round 5
// baseline (speedup 1.0000x reference)
#include <cuda_runtime.h>
#include <cuda_fp16.h>

#define K_CAPS 10
#define B_SZ   256
#define N_IN   1152
#define IC     8
#define OC     16

// fp16 scratch for u_hat: 10*256*1152*16 halves = 94.4 MB, layout [k][b][n][o]
__device__ __half2 g_uhat[(size_t)K_CAPS * B_SZ * N_IN * OC / 2];

// ---------------------------------------------------------------------------
// Kernel 1: u_hat[k,b,n,:] = u[b,n,:] @ W[k,n,:,:], fp32 math, fp16 store.
// grid (18,4,10), 256 threads. Thread = (n within 64-tile, o-quad).
// W slice (32 floats) register-cached across the 64-b loop.
// Warp store: 8 n x 4 q x 8B = 256B contiguous STG.64.
// ---------------------------------------------------------------------------
__global__ __launch_bounds__(256) void uhat_kernel(const float* __restrict__ u,
                                                   const float* __restrict__ W) {
    const int q  = threadIdx.x & 3;
    const int nl = threadIdx.x >> 2;
    const int n  = blockIdx.x * 64 + nl;
    const int b0 = blockIdx.y * 64;
    const int k  = blockIdx.z;

    const float4* Wv = reinterpret_cast<const float4*>(
        W + ((size_t)k * N_IN + n) * (IC * OC)) + q;
    float4 wr[8];
#pragma unroll
    for (int i = 0; i < 8; i++) wr[i] = __ldg(Wv + i * 4);

    const float4* uv   = reinterpret_cast<const float4*>(u);
    uint2*        outv = reinterpret_cast<uint2*>(g_uhat);

#pragma unroll 4
    for (int bb = 0; bb < 64; bb++) {
        const int b = b0 + bb;
        const size_t ui = ((size_t)b * N_IN + n) * 2;
        const float4 ua = __ldg(uv + ui);
        const float4 ub = __ldg(uv + ui + 1);
        const float uu[8] = {ua.x, ua.y, ua.z, ua.w, ub.x, ub.y, ub.z, ub.w};

        float4 acc = make_float4(0.f, 0.f, 0.f, 0.f);
#pragma unroll
        for (int i = 0; i < 8; i++) {
            acc.x = fmaf(uu[i], wr[i].x, acc.x);
            acc.y = fmaf(uu[i], wr[i].y, acc.y);
            acc.z = fmaf(uu[i], wr[i].z, acc.z);
            acc.w = fmaf(uu[i], wr[i].w, acc.w);
        }
        const __half2 h0 = __float22half2_rn(make_float2(acc.x, acc.y));
        const __half2 h1 = __float22half2_rn(make_float2(acc.z, acc.w));
        uint2 pk;
        pk.x = *reinterpret_cast<const unsigned int*>(&h0);
        pk.y = *reinterpret_cast<const unsigned int*>(&h1);
        outv[(((size_t)k * B_SZ + b) * N_IN + n) * 4 + q] = pk;
    }
}

// ---------------------------------------------------------------------------
// Kernel 2: routing, register-resident u_hat (fp16 load -> fp32 regs).
// One CTA per (k,b), 384 threads, 2 CTAs/SM.
// lane = 4*rsub + q: thread owns o-quad q of rows 8*(wid*12+s)+rsub, s=0..11.
// Global read once, coalesced (warp LDG.64 = 256B contiguous); 5 passes from regs.
// ---------------------------------------------------------------------------
__global__ __launch_bounds__(384, 2) void routing_kernel(float* __restrict__ out) {
    const int kb   = blockIdx.x;                      // k*256 + b
    const uint2* uh = reinterpret_cast<const uint2*>(g_uhat)
                      + (size_t)kb * (N_IN * 4);
    const int t    = threadIdx.x;
    const int wid  = t >> 5;
    const int lane = t & 31;
    const int q    = lane & 3;       // o-quad: columns 4q..4q+3
    const int rsub = lane >> 2;      // row within 8-row group

    __shared__ float sj[12][20];     // [warp][o(0..15), esum] (padded)
    __shared__ float sv[16];         // v_j broadcast
    __shared__ float sred[12];       // per-warp max partials
    __shared__ float sbc;            // block max broadcast

    // ---- one-time load: 12 coalesced LDG.64 per thread, widen to fp32 ----
    float4 r[12];
#pragma unroll
    for (int s = 0; s < 12; s++) {
        const int n = 8 * (wid * 12 + s) + rsub;
        const uint2 v = __ldg(uh + n * 4 + q);
        const __half2 h0 = *reinterpret_cast<const __half2*>(&v.x);
        const __half2 h1 = *reinterpret_cast<const __half2*>(&v.y);
        const float2 f0 = __half22float2(h0);
        const float2 f1 = __half22float2(h1);
        r[s] = make_float4(f0.x, f0.y, f1.x, f1.y);
    }
    float blog[12];
#pragma unroll
    for (int s = 0; s < 12; s++) blog[s] = 0.f;

    for (int it = 0; it < 3; it++) {
        // ---- s-pass: weighted accumulate into this thread's o-quad ----
        float4 acc = make_float4(0.f, 0.f, 0.f, 0.f);
        float esum = 0.f;
        if (it == 0) {
#pragma unroll
            for (int s = 0; s < 12; s++) {
                acc.x += r[s].x; acc.y += r[s].y;
                acc.z += r[s].z; acc.w += r[s].w;
            }
        } else {
            const float m = sbc;
#pragma unroll
            for (int s = 0; s < 12; s++) {
                const float w = __expf(blog[s] - m);
                esum += (q == 0) ? w : 0.f;   // count each row once
                acc.x = fmaf(w, r[s].x, acc.x);
                acc.y = fmaf(w, r[s].y, acc.y);
                acc.z = fmaf(w, r[s].z, acc.z);
                acc.w = fmaf(w, r[s].w, acc.w);
            }
        }
        // reduce over lanes sharing the same q (offsets 4,8,16); esum rides along
#pragma unroll
        for (int off = 4; off <= 16; off <<= 1) {
            acc.x += __shfl_xor_sync(0xffffffffu, acc.x, off);
            acc.y += __shfl_xor_sync(0xffffffffu, acc.y, off);
            acc.z += __shfl_xor_sync(0xffffffffu, acc.z, off);
            acc.w += __shfl_xor_sync(0xffffffffu, acc.w, off);
            esum  += __shfl_xor_sync(0xffffffffu, esum,  off);
        }
        if (lane < 4) {                       // lanes 0..3 hold o = 4q..4q+3
            sj[wid][4 * q + 0] = acc.x;
            sj[wid][4 * q + 1] = acc.y;
            sj[wid][4 * q + 2] = acc.z;
            sj[wid][4 * q + 3] = acc.w;
        }
        if (lane == 0) sj[wid][16] = esum;
        __syncthreads();

        // ---- warp 0: cross-warp reduce (17 values x 12 warps), squash ----
        if (wid == 0) {
            float val = 0.f;
            if (lane < 17) {
#pragma unroll
                for (int ww = 0; ww < 12; ww++) val += sj[ww][lane];
            }
            const float Z = __shfl_sync(0xffffffffu, val, 16);
            const float invZ = (it == 0) ? (1.f / (float)N_IN) : (1.f / Z);
            float s_ = (lane < 16) ? val * invZ : 0.f;
            float sq = s_ * s_;
#pragma unroll
            for (int off = 8; off; off >>= 1)
                sq += __shfl_xor_sync(0xffffffffu, sq, off);
            const float scale = sqrtf(sq) / (1.f + sq);   // squash factor
            const float v = s_ * scale;
            if (lane < 16) {
                if (it == 2) out[(size_t)kb * OC + lane] = v;
                else         sv[lane] = v;
            }
        }
        __syncthreads();

        // ---- a-pass + block max (iterations 0,1 only) ----
        if (it < 2) {
            const float4 vq = reinterpret_cast<const float4*>(sv)[q];
            float mymax = -3.402823466e+38f;
#pragma unroll
            for (int s = 0; s < 12; s++) {
                float d = r[s].x * vq.x;
                d = fmaf(r[s].y, vq.y, d);
                d = fmaf(r[s].z, vq.z, d);
                d = fmaf(r[s].w, vq.w, d);
                // sum over the 4 q-lanes of this row (bit-identical on all 4)
                d += __shfl_xor_sync(0xffffffffu, d, 1);
                d += __shfl_xor_sync(0xffffffffu, d, 2);
                blog[s] += d;
                mymax = fmaxf(mymax, blog[s]);
            }
#pragma unroll
            for (int off = 16; off; off >>= 1)
                mymax = fmaxf(mymax, __shfl_xor_sync(0xffffffffu, mymax, off));
            if (lane == 0) sred[wid] = mymax;
            __syncthreads();
            if (t == 0) {
                float mm = sred[0];
#pragma unroll
                for (int i = 1; i < 12; i++) mm = fmaxf(mm, sred[i]);
                sbc = mm;
            }
            __syncthreads();
        }
    }
}

// ---------------------------------------------------------------------------
extern "C" void kernel_launch(void* const* d_in, const int* in_sizes, int n_in,
                              void* d_out, int out_size) {
    const float* u = (const float*)d_in[0];
    const float* W = (const float*)d_in[1];
    if (in_sizes[0] == K_CAPS * N_IN * IC * OC) {   // robust to input ordering
        W = (const float*)d_in[0];
        u = (const float*)d_in[1];
    }
    uhat_kernel<<<dim3(N_IN / 64, B_SZ / 64, K_CAPS), 256>>>(u, W);
    routing_kernel<<<K_CAPS * B_SZ, 384>>>((float*)d_out);
}

// round 6
// speedup vs baseline: 1.5732x; 1.5732x over previous
#include <cuda_runtime.h>
#include <cuda_fp16.h>

#define K_CAPS 10
#define B_SZ   256
#define N_IN   1152
#define IC     8
#define OC     16

// fp16 scratch for u_hat: 10*256*1152*16 halves = 94.4 MB, layout [k][b][n][o]
__device__ __half2 g_uhat[(size_t)K_CAPS * B_SZ * N_IN * OC / 2];

// ---- packed f32x2 helpers (sm_103a FFMA2 path, PTX-only) -------------------
__device__ __forceinline__ unsigned long long pk2(float lo, float hi) {
    unsigned long long r;
    asm("mov.b64 %0, {%1, %2};" : "=l"(r) : "f"(lo), "f"(hi));
    return r;
}
__device__ __forceinline__ unsigned long long fma2(unsigned long long a,
                                                   unsigned long long b,
                                                   unsigned long long c) {
    unsigned long long d;
    asm("fma.rn.f32x2 %0, %1, %2, %3;" : "=l"(d) : "l"(a), "l"(b), "l"(c));
    return d;
}
__device__ __forceinline__ float2 unpk2(unsigned long long v) {
    float2 f;
    asm("mov.b64 {%0, %1}, %2;" : "=f"(f.x), "=f"(f.y) : "l"(v));
    return f;
}

// ---------------------------------------------------------------------------
// Kernel 1: u_hat[k,b,n,:] = u[b,n,:] @ W[k,n,:,:], f32x2 math, fp16 store.
// grid (18,4,10), 256 threads. Thread = (n within 64-tile, o-quad).
// W slice register-cached as 16 packed f32x2 across the 64-b loop.
// ---------------------------------------------------------------------------
__global__ __launch_bounds__(256) void uhat_kernel(const float* __restrict__ u,
                                                   const float* __restrict__ W) {
    const int q  = threadIdx.x & 3;
    const int nl = threadIdx.x >> 2;
    const int n  = blockIdx.x * 64 + nl;
    const int b0 = blockIdx.y * 64;
    const int k  = blockIdx.z;

    const float4* Wv = reinterpret_cast<const float4*>(
        W + ((size_t)k * N_IN + n) * (IC * OC)) + q;
    unsigned long long w01[8], w23[8];
#pragma unroll
    for (int i = 0; i < 8; i++) {
        const float4 wv = __ldg(Wv + i * 4);
        w01[i] = pk2(wv.x, wv.y);
        w23[i] = pk2(wv.z, wv.w);
    }

    const float4* uv   = reinterpret_cast<const float4*>(u);
    uint2*        outv = reinterpret_cast<uint2*>(g_uhat);

#pragma unroll 4
    for (int bb = 0; bb < 64; bb++) {
        const int b = b0 + bb;
        const size_t ui = ((size_t)b * N_IN + n) * 2;
        const float4 ua = __ldg(uv + ui);
        const float4 ub = __ldg(uv + ui + 1);
        const float uu[8] = {ua.x, ua.y, ua.z, ua.w, ub.x, ub.y, ub.z, ub.w};

        unsigned long long a01 = 0ull, a23 = 0ull;   // (+0.0f, +0.0f)
#pragma unroll
        for (int i = 0; i < 8; i++) {
            const unsigned long long up = pk2(uu[i], uu[i]);
            a01 = fma2(up, w01[i], a01);
            a23 = fma2(up, w23[i], a23);
        }
        const float2 f01 = unpk2(a01);
        const float2 f23 = unpk2(a23);
        const __half2 h0 = __float22half2_rn(f01);
        const __half2 h1 = __float22half2_rn(f23);
        uint2 pk;
        pk.x = *reinterpret_cast<const unsigned int*>(&h0);
        pk.y = *reinterpret_cast<const unsigned int*>(&h1);
        outv[(((size_t)k * B_SZ + b) * N_IN + n) * 4 + q] = pk;
    }
}

// ---------------------------------------------------------------------------
// Kernel 2: routing, register-resident u_hat (fp16 load -> fp32 regs, PINNED).
// One CTA per (k,b), 384 threads, 2 CTAs/SM.
// lane = 4*rsub + q: thread owns o-quad q of rows 8*(wid*12+s)+rsub, s=0..11.
// ---------------------------------------------------------------------------
__global__ __launch_bounds__(384, 2) void routing_kernel(float* __restrict__ out) {
    const int kb   = blockIdx.x;                      // k*256 + b
    const uint2* uh = reinterpret_cast<const uint2*>(g_uhat)
                      + (size_t)kb * (N_IN * 4);
    const int t    = threadIdx.x;
    const int wid  = t >> 5;
    const int lane = t & 31;
    const int q    = lane & 3;       // o-quad: columns 4q..4q+3
    const int rsub = lane >> 2;      // row within 8-row group

    __shared__ float sj[12][20];     // [warp][o(0..15), esum] (padded)
    __shared__ float sv[16];         // v_j broadcast
    __shared__ float sred[12];       // per-warp max partials
    __shared__ float sbc;            // block max broadcast

    // ---- one-time load, widen to fp32, PIN so ptxas cannot rematerialize ----
    float4 r[12];
#pragma unroll
    for (int s = 0; s < 12; s++) {
        const int n = 8 * (wid * 12 + s) + rsub;
        const uint2 v = __ldg(uh + n * 4 + q);
        const __half2 h0 = *reinterpret_cast<const __half2*>(&v.x);
        const __half2 h1 = *reinterpret_cast<const __half2*>(&v.y);
        const float2 f0 = __half22float2(h0);
        const float2 f1 = __half22float2(h1);
        r[s] = make_float4(f0.x, f0.y, f1.x, f1.y);
        asm volatile("" : "+f"(r[s].x), "+f"(r[s].y), "+f"(r[s].z), "+f"(r[s].w));
    }
    float blog[12];
#pragma unroll
    for (int s = 0; s < 12; s++) blog[s] = 0.f;

    for (int it = 0; it < 3; it++) {
        // ---- s-pass: weighted accumulate into this thread's o-quad ----
        float4 acc = make_float4(0.f, 0.f, 0.f, 0.f);
        float esum = 0.f;
        if (it == 0) {
#pragma unroll
            for (int s = 0; s < 12; s++) {
                acc.x += r[s].x; acc.y += r[s].y;
                acc.z += r[s].z; acc.w += r[s].w;
            }
        } else {
            const float m = sbc;
#pragma unroll
            for (int s = 0; s < 12; s++) {
                const float w = __expf(blog[s] - m);
                esum += (q == 0) ? w : 0.f;   // count each row once
                acc.x = fmaf(w, r[s].x, acc.x);
                acc.y = fmaf(w, r[s].y, acc.y);
                acc.z = fmaf(w, r[s].z, acc.z);
                acc.w = fmaf(w, r[s].w, acc.w);
            }
        }
        // reduce over lanes sharing the same q (offsets 4,8,16); esum rides along
#pragma unroll
        for (int off = 4; off <= 16; off <<= 1) {
            acc.x += __shfl_xor_sync(0xffffffffu, acc.x, off);
            acc.y += __shfl_xor_sync(0xffffffffu, acc.y, off);
            acc.z += __shfl_xor_sync(0xffffffffu, acc.z, off);
            acc.w += __shfl_xor_sync(0xffffffffu, acc.w, off);
            esum  += __shfl_xor_sync(0xffffffffu, esum,  off);
        }
        if (lane < 4) {                       // lanes 0..3 hold o = 4q..4q+3
            sj[wid][4 * q + 0] = acc.x;
            sj[wid][4 * q + 1] = acc.y;
            sj[wid][4 * q + 2] = acc.z;
            sj[wid][4 * q + 3] = acc.w;
        }
        if (lane == 0) sj[wid][16] = esum;
        __syncthreads();

        // ---- warp 0: cross-warp reduce (17 values x 12 warps), squash ----
        if (wid == 0) {
            float val = 0.f;
            if (lane < 17) {
#pragma unroll
                for (int ww = 0; ww < 12; ww++) val += sj[ww][lane];
            }
            const float Z = __shfl_sync(0xffffffffu, val, 16);
            const float invZ = (it == 0) ? (1.f / (float)N_IN) : (1.f / Z);
            float s_ = (lane < 16) ? val * invZ : 0.f;
            float sq = s_ * s_;
#pragma unroll
            for (int off = 8; off; off >>= 1)
                sq += __shfl_xor_sync(0xffffffffu, sq, off);
            const float scale = sqrtf(sq) / (1.f + sq);   // squash factor
            const float v = s_ * scale;
            if (lane < 16) {
                if (it == 2) out[(size_t)kb * OC + lane] = v;
                else         sv[lane] = v;
            }
        }
        __syncthreads();

        // ---- a-pass + block max (iterations 0,1 only) ----
        if (it < 2) {
            const float4 vq = reinterpret_cast<const float4*>(sv)[q];
            float mymax = -3.402823466e+38f;
#pragma unroll
            for (int s = 0; s < 12; s++) {
                float d = r[s].x * vq.x;
                d = fmaf(r[s].y, vq.y, d);
                d = fmaf(r[s].z, vq.z, d);
                d = fmaf(r[s].w, vq.w, d);
                // sum over the 4 q-lanes of this row (bit-identical on all 4)
                d += __shfl_xor_sync(0xffffffffu, d, 1);
                d += __shfl_xor_sync(0xffffffffu, d, 2);
                blog[s] += d;
                mymax = fmaxf(mymax, blog[s]);
            }
#pragma unroll
            for (int off = 16; off; off >>= 1)
                mymax = fmaxf(mymax, __shfl_xor_sync(0xffffffffu, mymax, off));
            if (lane == 0) sred[wid] = mymax;
            __syncthreads();
            if (t == 0) {
                float mm = sred[0];
#pragma unroll
                for (int i = 1; i < 12; i++) mm = fmaxf(mm, sred[i]);
                sbc = mm;
            }
            __syncthreads();
        }
    }
}

// ---------------------------------------------------------------------------
extern "C" void kernel_launch(void* const* d_in, const int* in_sizes, int n_in,
                              void* d_out, int out_size) {
    const float* u = (const float*)d_in[0];
    const float* W = (const float*)d_in[1];
    if (in_sizes[0] == K_CAPS * N_IN * IC * OC) {   // robust to input ordering
        W = (const float*)d_in[0];
        u = (const float*)d_in[1];
    }
    uhat_kernel<<<dim3(N_IN / 64, B_SZ / 64, K_CAPS), 256>>>(u, W);
    routing_kernel<<<K_CAPS * B_SZ, 384>>>((float*)d_out);
}

// round 8
// speedup vs baseline: 1.6583x; 1.0541x over previous
#include <cuda_runtime.h>
#include <cuda_fp16.h>

#define K_CAPS 10
#define B_SZ   256
#define N_IN   1152
#define IC     8
#define OC     16

// fp16 scratch for u_hat: 10*256*1152*16 halves = 94.4 MB, layout [k][b][n][o]
__device__ __half2 g_uhat[(size_t)K_CAPS * B_SZ * N_IN * OC / 2];

// ---- packed f32x2 helpers (sm_103a FFMA2 path, PTX-only) -------------------
__device__ __forceinline__ unsigned long long pk2(float lo, float hi) {
    unsigned long long r;
    asm("mov.b64 %0, {%1, %2};" : "=l"(r) : "f"(lo), "f"(hi));
    return r;
}
__device__ __forceinline__ unsigned long long fma2(unsigned long long a,
                                                   unsigned long long b,
                                                   unsigned long long c) {
    unsigned long long d;
    asm("fma.rn.f32x2 %0, %1, %2, %3;" : "=l"(d) : "l"(a), "l"(b), "l"(c));
    return d;
}
__device__ __forceinline__ float2 unpk2(unsigned long long v) {
    float2 f;
    asm("mov.b64 {%0, %1}, %2;" : "=f"(f.x), "=f"(f.y) : "l"(v));
    return f;
}

// ---------------------------------------------------------------------------
// Kernel 1: u_hat[k,b,n,:] = u[b,n,:] @ W[k,n,:,:], f32x2 math, fp16 store.
// (unchanged from R6)
// ---------------------------------------------------------------------------
__global__ __launch_bounds__(256) void uhat_kernel(const float* __restrict__ u,
                                                   const float* __restrict__ W) {
    const int q  = threadIdx.x & 3;
    const int nl = threadIdx.x >> 2;
    const int n  = blockIdx.x * 64 + nl;
    const int b0 = blockIdx.y * 64;
    const int k  = blockIdx.z;

    const float4* Wv = reinterpret_cast<const float4*>(
        W + ((size_t)k * N_IN + n) * (IC * OC)) + q;
    unsigned long long w01[8], w23[8];
#pragma unroll
    for (int i = 0; i < 8; i++) {
        const float4 wv = __ldg(Wv + i * 4);
        w01[i] = pk2(wv.x, wv.y);
        w23[i] = pk2(wv.z, wv.w);
    }

    const float4* uv   = reinterpret_cast<const float4*>(u);
    uint2*        outv = reinterpret_cast<uint2*>(g_uhat);

#pragma unroll 4
    for (int bb = 0; bb < 64; bb++) {
        const int b = b0 + bb;
        const size_t ui = ((size_t)b * N_IN + n) * 2;
        const float4 ua = __ldg(uv + ui);
        const float4 ub = __ldg(uv + ui + 1);
        const float uu[8] = {ua.x, ua.y, ua.z, ua.w, ub.x, ub.y, ub.z, ub.w};

        unsigned long long a01 = 0ull, a23 = 0ull;   // (+0.0f, +0.0f)
#pragma unroll
        for (int i = 0; i < 8; i++) {
            const unsigned long long up = pk2(uu[i], uu[i]);
            a01 = fma2(up, w01[i], a01);
            a23 = fma2(up, w23[i], a23);
        }
        const float2 f01 = unpk2(a01);
        const float2 f23 = unpk2(a23);
        const __half2 h0 = __float22half2_rn(f01);
        const __half2 h1 = __float22half2_rn(f23);
        uint2 pk;
        pk.x = *reinterpret_cast<const unsigned int*>(&h0);
        pk.y = *reinterpret_cast<const unsigned int*>(&h1);
        outv[(((size_t)k * B_SZ + b) * N_IN + n) * 4 + q] = pk;
    }
}

// ---------------------------------------------------------------------------
// Kernel 2 v3: routing, 576 threads (18 warps), 8 row-quads/thread, 2 CTA/SM.
// lane = 4*rsub + q: thread owns o-quad q of rows 8*(wid*8+s)+rsub, s=0..7.
// No max-subtraction in softmax (|blog| <= ~40, exp safe in fp32, ratio exact).
// a-pass fused into s-pass: 3 sweeps total, all from pinned fp32 registers.
// ---------------------------------------------------------------------------
__global__ __launch_bounds__(576, 2) void routing_kernel(float* __restrict__ out) {
    const int kb   = blockIdx.x;                      // k*256 + b
    const uint2* uh = reinterpret_cast<const uint2*>(g_uhat)
                      + (size_t)kb * (N_IN * 4);
    const int t    = threadIdx.x;
    const int wid  = t >> 5;
    const int lane = t & 31;
    const int q    = lane & 3;       // o-quad: columns 4q..4q+3
    const int rsub = lane >> 2;      // row within 8-row group

    __shared__ float sj[18][20];     // [warp][o(0..15), esum] (padded)
    __shared__ float sv[16];         // v_j broadcast

    // ---- one-time load, widen to fp32, PIN so ptxas cannot rematerialize ----
    float4 r[8];
#pragma unroll
    for (int s = 0; s < 8; s++) {
        const int n = 8 * (wid * 8 + s) + rsub;
        const uint2 v = __ldg(uh + n * 4 + q);
        const __half2 h0 = *reinterpret_cast<const __half2*>(&v.x);
        const __half2 h1 = *reinterpret_cast<const __half2*>(&v.y);
        const float2 f0 = __half22float2(h0);
        const float2 f1 = __half22float2(h1);
        r[s] = make_float4(f0.x, f0.y, f1.x, f1.y);
        asm volatile("" : "+f"(r[s].x), "+f"(r[s].y), "+f"(r[s].z), "+f"(r[s].w));
    }
    float blog[8];
#pragma unroll
    for (int s = 0; s < 8; s++) blog[s] = 0.f;

    for (int it = 0; it < 3; it++) {
        // ---- fused (a + s) sweep over this thread's 8 rows ----
        float4 acc = make_float4(0.f, 0.f, 0.f, 0.f);
        float esum = 0.f;
        if (it == 0) {
#pragma unroll
            for (int s = 0; s < 8; s++) {
                acc.x += r[s].x; acc.y += r[s].y;
                acc.z += r[s].z; acc.w += r[s].w;
            }
        } else {
            const float4 vq = reinterpret_cast<const float4*>(sv)[q];
#pragma unroll
            for (int s = 0; s < 8; s++) {
                float d = r[s].x * vq.x;
                d = fmaf(r[s].y, vq.y, d);
                d = fmaf(r[s].z, vq.z, d);
                d = fmaf(r[s].w, vq.w, d);
                // full row dot: sum over the 4 q-lanes (bit-identical on all 4)
                d += __shfl_xor_sync(0xffffffffu, d, 1);
                d += __shfl_xor_sync(0xffffffffu, d, 2);
                blog[s] += d;
                const float w = __expf(blog[s]);      // no max-sub: |blog|<=~40
                esum += (q == 0) ? w : 0.f;           // count each row once
                acc.x = fmaf(w, r[s].x, acc.x);
                acc.y = fmaf(w, r[s].y, acc.y);
                acc.z = fmaf(w, r[s].z, acc.z);
                acc.w = fmaf(w, r[s].w, acc.w);
            }
        }
        // reduce over lanes sharing the same q (offsets 4,8,16); esum rides along
#pragma unroll
        for (int off = 4; off <= 16; off <<= 1) {
            acc.x += __shfl_xor_sync(0xffffffffu, acc.x, off);
            acc.y += __shfl_xor_sync(0xffffffffu, acc.y, off);
            acc.z += __shfl_xor_sync(0xffffffffu, acc.z, off);
            acc.w += __shfl_xor_sync(0xffffffffu, acc.w, off);
            esum  += __shfl_xor_sync(0xffffffffu, esum,  off);
        }
        if (lane < 4) {                       // lanes 0..3 hold o = 4q..4q+3
            sj[wid][4 * q + 0] = acc.x;
            sj[wid][4 * q + 1] = acc.y;
            sj[wid][4 * q + 2] = acc.z;
            sj[wid][4 * q + 3] = acc.w;
        }
        if (lane == 0) sj[wid][16] = esum;
        __syncthreads();

        // ---- warp 0: cross-warp reduce (17 values x 18 warps), squash ----
        if (wid == 0) {
            float val = 0.f;
            if (lane < 17) {
#pragma unroll
                for (int ww = 0; ww < 18; ww++) val += sj[ww][lane];
            }
            const float Z = __shfl_sync(0xffffffffu, val, 16);
            const float invZ = (it == 0) ? (1.f / (float)N_IN) : (1.f / Z);
            float s_ = (lane < 16) ? val * invZ : 0.f;
            float sq = s_ * s_;
#pragma unroll
            for (int off = 8; off; off >>= 1)
                sq += __shfl_xor_sync(0xffffffffu, sq, off);
            const float scale = sqrtf(sq) / (1.f + sq);   // squash factor
            const float v = s_ * scale;
            if (lane < 16) {
                if (it == 2) out[(size_t)kb * OC + lane] = v;
                else         sv[lane] = v;
            }
        }
        __syncthreads();
    }
}

// ---------------------------------------------------------------------------
extern "C" void kernel_launch(void* const* d_in, const int* in_sizes, int n_in,
                              void* d_out, int out_size) {
    const float* u = (const float*)d_in[0];
    const float* W = (const float*)d_in[1];
    if (in_sizes[0] == K_CAPS * N_IN * IC * OC) {   // robust to input ordering
        W = (const float*)d_in[0];
        u = (const float*)d_in[1];
    }
    uhat_kernel<<<dim3(N_IN / 64, B_SZ / 64, K_CAPS), 256>>>(u, W);
    routing_kernel<<<K_CAPS * B_SZ, 576>>>((float*)d_out);
}